// round 10
// baseline (speedup 1.0000x reference)
#include <cuda_runtime.h>
#include <cstdint>

// Problem constants
#define BB   16
#define NN   8192
#define CIN  3
#define HID  64
#define DD   256
#define KK   4
#define GHID 128
#define DOUT 128
#define TILE 128
#define NTILES (NN / TILE)   // 64
#define NITEMS (NTILES * KK * BB)   // 4096
#define PBLOCKS 444                 // 148 SMs * 3 CTAs

// ---------------- device scratch (static, no allocations) ----------------
__device__ int      g_cnt[BB * KK];
__device__ int      g_idx[BB * KK * NN];       // per (b,k) index lists
__device__ unsigned g_maxu[BB * DD];           // flipped-float max slots

// ---------------- helpers ----------------
__device__ __forceinline__ float gelu_exact(float x) {
    return 0.5f * x * (1.0f + erff(x * 0.7071067811865476f));
}

__device__ __forceinline__ unsigned long long fma2(unsigned long long a,
                                                   unsigned long long b,
                                                   unsigned long long c) {
    unsigned long long d;
    asm("fma.rn.f32x2 %0, %1, %2, %3;" : "=l"(d) : "l"(a), "l"(b), "l"(c));
    return d;
}

__device__ __forceinline__ unsigned long long dup2(float v) {
    unsigned long long r;
    asm("mov.b64 %0, {%1, %1};" : "=l"(r) : "f"(v));
    return r;
}

__device__ __forceinline__ void unpack2(unsigned long long v, float& lo, float& hi) {
    asm("mov.b64 {%0, %1}, %2;" : "=f"(lo), "=f"(hi) : "l"(v));
}

// order-preserving float -> uint mapping (for exact atomic max)
__device__ __forceinline__ unsigned flip_f32(float f) {
    unsigned u = __float_as_uint(f);
    return (u & 0x80000000u) ? ~u : (u | 0x80000000u);
}
__device__ __forceinline__ float unflip_f32(unsigned e) {
    unsigned u = (e & 0x80000000u) ? (e ^ 0x80000000u) : ~e;
    return __uint_as_float(u);
}

// ---------------- K0: reset scratch ----------------
__global__ void k0_init() {
    int i = blockIdx.x * 256 + threadIdx.x;
    if (i < BB * KK) g_cnt[i] = 0;
    if (i < BB * DD) g_maxu[i] = 0u;   // below all finite flipped floats
}

// ---------------- K1: argmax classify + compaction ----------------
__global__ void k1_classify(const float* __restrict__ lab) {
    __shared__ int scnt[KK];
    __shared__ int sbase[KK];
    int t   = threadIdx.x;
    int gid = blockIdx.x * 256 + t;
    int b   = gid / NN;
    int n   = gid % NN;

    if (t < KK) scnt[t] = 0;
    __syncthreads();

    const float* lb = lab + (size_t)b * KK * NN + n;
    float l0 = lb[0], l1 = lb[NN], l2 = lb[2 * NN], l3 = lb[3 * NN];
    int k = 0; float best = l0;
    if (l1 > best) { best = l1; k = 1; }
    if (l2 > best) { best = l2; k = 2; }
    if (l3 > best) { best = l3; k = 3; }

    int pos = atomicAdd(&scnt[k], 1);
    __syncthreads();
    if (t < KK) sbase[t] = atomicAdd(&g_cnt[b * KK + t], scnt[t]);
    __syncthreads();
    g_idx[(b * KK + k) * NN + sbase[k] + pos] = n;
}

// ---------------- K2: PERSISTENT branch MLP + fused per-batch max ----------------
// Exactly 444 blocks (3 CTAs x 148 SMs), 256 threads. Each block strides the
// 4096-item space (item = tile*64 + k*16 + b, tile-major so real items are
// contiguous and stride-444 assignment load-balances). Inner loop identical
// to R8: 8 dims x 4 points per thread, 4 point passes, software-pipelined kk.
__global__ __launch_bounds__(256, 3)
void k2_main(const float* __restrict__ x,
             const float* __restrict__ W1, const float* __restrict__ b1,
             const float* __restrict__ W2, const float* __restrict__ b2) {
    __shared__ __align__(16) float sh_ht[HID][TILE];   // 32 KB
    __shared__ float sh_x0[TILE], sh_x1[TILE], sh_x2[TILE];
    __shared__ int   sh_idx[TILE];
    __shared__ float sh_w1[CIN * HID];
    __shared__ float sh_b1[HID];

    const int t     = threadIdx.x;
    const int dtile = t >> 3;       // 0..31
    const int prow  = t & 7;        // 0..7
    const int d0    = dtile * 8;

    for (int item = blockIdx.x; item < NITEMS; item += PBLOCKS) {
        const int tile = item >> 6;
        const int rem  = item & 63;
        const int kb   = rem >> 4;
        const int b    = rem & 15;

        const int cnt   = g_cnt[b * KK + kb];
        const int start = tile * TILE;
        if (start >= cnt) continue;           // uniform branch, no smem touched
        const int npts = min(TILE, cnt - start);

        __syncthreads();   // previous item's phase-2 reads done before overwrite

        if (t < TILE && t < npts) sh_idx[t] = g_idx[(b * KK + kb) * NN + start + t];
        if (t < CIN * HID)        sh_w1[t]  = W1[kb * CIN * HID + t];
        if (t < HID)              sh_b1[t]  = b1[kb * HID + t];
        __syncthreads();

        if (t < npts) {
            int n = sh_idx[t];
            const float* xb = x + (size_t)b * CIN * NN;
            sh_x0[t] = xb[n];
            sh_x1[t] = xb[NN + n];
            sh_x2[t] = xb[2 * NN + n];
        }
        __syncthreads();

        // ---- phase 1: lane = point, jg = t>>5 covers 8 j's; zero-fill tail
        {
            const int lane = t & 31;
            const int jg   = t >> 5;            // 0..7
            #pragma unroll
            for (int pass = 0; pass < TILE / 32; pass++) {
                int pp = pass * 32 + lane;
                if (pp < npts) {
                    float x0 = sh_x0[pp], x1 = sh_x1[pp], x2 = sh_x2[pp];
                    #pragma unroll
                    for (int jj = 0; jj < 8; jj++) {
                        int j = jg * 8 + jj;
                        float v = fmaf(x0, sh_w1[j],
                                  fmaf(x1, sh_w1[HID + j],
                                  fmaf(x2, sh_w1[2 * HID + j], sh_b1[j])));
                        sh_ht[j][pp] = gelu_exact(v);
                    }
                } else {
                    #pragma unroll
                    for (int jj = 0; jj < 8; jj++)
                        sh_ht[jg * 8 + jj][pp] = 0.0f;
                }
            }
        }
        __syncthreads();

        // ---- phase 2: 8 dims x 4 points per thread, 4 passes, pipelined kk
        const float* wbase = W2 + ((size_t)kb * HID) * DD + d0;

        float mx[8];
        #pragma unroll
        for (int c = 0; c < 8; c++) mx[c] = -3.402823466e38f;

        #pragma unroll 1
        for (int pass = 0; pass < TILE / 32; pass++) {
            const int p0 = pass * 32 + prow * 4;
            const float* hcol = &sh_ht[0][p0];

            unsigned long long acc[4][4];   // [point][dim-pair]
            #pragma unroll
            for (int p = 0; p < 4; p++)
                #pragma unroll
                for (int c = 0; c < 4; c++) acc[p][c] = 0ull;

            // prologue: load kk = 0
            float4 ha      = *reinterpret_cast<const float4*>(hcol);
            ulonglong2 w03 = *reinterpret_cast<const ulonglong2*>(wbase);
            ulonglong2 w47 = *reinterpret_cast<const ulonglong2*>(wbase + 4);

            #pragma unroll 1
            for (int kk = 0; kk < HID - 1; kk++) {
                const float4 hc     = ha;
                const ulonglong2 wA = w03;
                const ulonglong2 wB = w47;
                // prefetch next iteration (overlaps with the FMAs below)
                ha  = *reinterpret_cast<const float4*>(hcol + (size_t)(kk + 1) * TILE);
                w03 = *reinterpret_cast<const ulonglong2*>(wbase + (size_t)(kk + 1) * DD);
                w47 = *reinterpret_cast<const ulonglong2*>(wbase + (size_t)(kk + 1) * DD + 4);

                const unsigned long long h0 = dup2(hc.x), h1 = dup2(hc.y),
                                         h2 = dup2(hc.z), h3 = dup2(hc.w);
                acc[0][0] = fma2(h0, wA.x, acc[0][0]);
                acc[0][1] = fma2(h0, wA.y, acc[0][1]);
                acc[0][2] = fma2(h0, wB.x, acc[0][2]);
                acc[0][3] = fma2(h0, wB.y, acc[0][3]);
                acc[1][0] = fma2(h1, wA.x, acc[1][0]);
                acc[1][1] = fma2(h1, wA.y, acc[1][1]);
                acc[1][2] = fma2(h1, wB.x, acc[1][2]);
                acc[1][3] = fma2(h1, wB.y, acc[1][3]);
                acc[2][0] = fma2(h2, wA.x, acc[2][0]);
                acc[2][1] = fma2(h2, wA.y, acc[2][1]);
                acc[2][2] = fma2(h2, wB.x, acc[2][2]);
                acc[2][3] = fma2(h2, wB.y, acc[2][3]);
                acc[3][0] = fma2(h3, wA.x, acc[3][0]);
                acc[3][1] = fma2(h3, wA.y, acc[3][1]);
                acc[3][2] = fma2(h3, wB.x, acc[3][2]);
                acc[3][3] = fma2(h3, wB.y, acc[3][3]);
            }
            // epilogue: kk = HID-1
            {
                const unsigned long long h0 = dup2(ha.x), h1 = dup2(ha.y),
                                         h2 = dup2(ha.z), h3 = dup2(ha.w);
                acc[0][0] = fma2(h0, w03.x, acc[0][0]);
                acc[0][1] = fma2(h0, w03.y, acc[0][1]);
                acc[0][2] = fma2(h0, w47.x, acc[0][2]);
                acc[0][3] = fma2(h0, w47.y, acc[0][3]);
                acc[1][0] = fma2(h1, w03.x, acc[1][0]);
                acc[1][1] = fma2(h1, w03.y, acc[1][1]);
                acc[1][2] = fma2(h1, w47.x, acc[1][2]);
                acc[1][3] = fma2(h1, w47.y, acc[1][3]);
                acc[2][0] = fma2(h2, w03.x, acc[2][0]);
                acc[2][1] = fma2(h2, w03.y, acc[2][1]);
                acc[2][2] = fma2(h2, w47.x, acc[2][2]);
                acc[2][3] = fma2(h2, w47.y, acc[2][3]);
                acc[3][0] = fma2(h3, w03.x, acc[3][0]);
                acc[3][1] = fma2(h3, w03.y, acc[3][1]);
                acc[3][2] = fma2(h3, w47.x, acc[3][2]);
                acc[3][3] = fma2(h3, w47.y, acc[3][3]);
            }

            // fold valid points of this pass into per-dim running max
            #pragma unroll
            for (int p = 0; p < 4; p++) {
                if (p0 + p < npts) {
                    #pragma unroll
                    for (int c = 0; c < 4; c++) {
                        float lo, hi; unpack2(acc[p][c], lo, hi);
                        mx[2 * c]     = fmaxf(mx[2 * c],     lo);
                        mx[2 * c + 1] = fmaxf(mx[2 * c + 1], hi);
                    }
                }
            }
        }

        // warp butterfly over prow bits (lanes sharing a dtile are adjacent)
        #pragma unroll
        for (int s = 1; s < 8; s <<= 1)
            #pragma unroll
            for (int c = 0; c < 8; c++)
                mx[c] = fmaxf(mx[c], __shfl_xor_sync(0xffffffffu, mx[c], s));

        if (prow == 0) {
            #pragma unroll
            for (int c = 0; c < 8; c++) {
                float v = mx[c] + b2[kb * DD + d0 + c];  // bias hoisted past max
                atomicMax(&g_maxu[b * DD + d0 + c], flip_f32(v));
            }
        }
    }
}

// ---------------- K3: global MLP on per-batch max ----------------
__global__ __launch_bounds__(1024, 1)
void k3_head(const float* __restrict__ Wg1, const float* __restrict__ bg1,
             const float* __restrict__ Wg2, const float* __restrict__ bg2,
             float* __restrict__ out) {
    __shared__ float sg[DD];
    __shared__ float part[1024];
    __shared__ float shg[GHID];
    const int b   = blockIdx.x;
    const int tid = threadIdx.x;
    const int t   = tid & 127;     // output unit
    const int g   = tid >> 7;      // j-split group 0..7

    if (tid < DD) sg[tid] = unflip_f32(g_maxu[b * DD + tid]);
    __syncthreads();

    // layer 1: 256 -> 128, each thread covers 32 j's
    {
        float acc = 0.0f;
        const int j0 = g * 32;
        #pragma unroll 16
        for (int j = 0; j < 32; j++)
            acc = fmaf(sg[j0 + j], Wg1[(j0 + j) * GHID + t], acc);
        part[tid] = acc;
    }
    __syncthreads();
    if (tid < GHID) {
        float v = bg1[tid];
        #pragma unroll
        for (int gg = 0; gg < 8; gg++) v += part[tid + 128 * gg];
        shg[tid] = gelu_exact(v);
    }
    __syncthreads();

    // layer 2: 128 -> 128, each thread covers 16 j's
    {
        float acc = 0.0f;
        const int j0 = g * 16;
        #pragma unroll 16
        for (int j = 0; j < 16; j++)
            acc = fmaf(shg[j0 + j], Wg2[(j0 + j) * DOUT + t], acc);
        part[tid] = acc;
    }
    __syncthreads();
    if (tid < DOUT) {
        float v = bg2[tid];
        #pragma unroll
        for (int gg = 0; gg < 8; gg++) v += part[tid + 128 * gg];
        out[b * DOUT + tid] = v;
    }
}

// ---------------- launch ----------------
extern "C" void kernel_launch(void* const* d_in, const int* in_sizes, int n_in,
                              void* d_out, int out_size) {
    const float* x     = (const float*)d_in[0];
    const float* xlab  = (const float*)d_in[1];
    const float* W1    = (const float*)d_in[2];
    const float* b1    = (const float*)d_in[3];
    const float* W2    = (const float*)d_in[4];
    const float* b2    = (const float*)d_in[5];
    const float* Wg1   = (const float*)d_in[6];
    const float* bg1   = (const float*)d_in[7];
    const float* Wg2   = (const float*)d_in[8];
    const float* bg2   = (const float*)d_in[9];
    float* out = (float*)d_out;

    k0_init<<<(BB * DD + 255) / 256, 256>>>();
    k1_classify<<<(BB * NN) / 256, 256>>>(xlab);
    k2_main<<<PBLOCKS, 256>>>(x, W1, b1, W2, b2);
    k3_head<<<BB, 1024>>>(Wg1, bg1, Wg2, bg2, out);
}

// round 12
// speedup vs baseline: 1.1604x; 1.1604x over previous
#include <cuda_runtime.h>
#include <cstdint>

// Problem constants
#define BB   16
#define NN   8192
#define CIN  3
#define HID  64
#define DD   256
#define KK   4
#define GHID 128
#define DOUT 128
#define TILE 128
#define NT   (NN / TILE)            // 64 tiles
#define SLOTS (NT * BB)             // 1024 (tile,b) slots per branch
#define BLKS_PER_KB 74
#define PBLOCKS (BLKS_PER_KB * KK)  // 296 = 2 CTAs x 148 SMs

// dynamic smem layout (bytes)
#define OFF_W2   0                  // [HID][DD] floats = 64 KB
#define OFF_HT   65536              // [HID][TILE] floats = 32 KB
#define OFF_X0   98304              // [TILE]
#define OFF_X1   98816
#define OFF_X2   99328
#define OFF_IDX  99840              // [TILE] int
#define OFF_W1   100352             // [CIN*HID]
#define OFF_B1   101120             // [HID]
#define K2_SMEM  101376

// ---------------- device scratch (static, no allocations) ----------------
__device__ int      g_cnt[BB * KK];
__device__ int      g_idx[BB * KK * NN];       // per (b,k) index lists
__device__ unsigned g_maxu[BB * DD];           // flipped-float max slots

// ---------------- helpers ----------------
__device__ __forceinline__ float gelu_exact(float x) {
    return 0.5f * x * (1.0f + erff(x * 0.7071067811865476f));
}

__device__ __forceinline__ unsigned long long fma2(unsigned long long a,
                                                   unsigned long long b,
                                                   unsigned long long c) {
    unsigned long long d;
    asm("fma.rn.f32x2 %0, %1, %2, %3;" : "=l"(d) : "l"(a), "l"(b), "l"(c));
    return d;
}

__device__ __forceinline__ unsigned long long dup2(float v) {
    unsigned long long r;
    asm("mov.b64 %0, {%1, %1};" : "=l"(r) : "f"(v));
    return r;
}

__device__ __forceinline__ void unpack2(unsigned long long v, float& lo, float& hi) {
    asm("mov.b64 {%0, %1}, %2;" : "=f"(lo), "=f"(hi) : "l"(v));
}

// order-preserving float -> uint mapping (for exact atomic max)
__device__ __forceinline__ unsigned flip_f32(float f) {
    unsigned u = __float_as_uint(f);
    return (u & 0x80000000u) ? ~u : (u | 0x80000000u);
}
__device__ __forceinline__ float unflip_f32(unsigned e) {
    unsigned u = (e & 0x80000000u) ? (e ^ 0x80000000u) : ~e;
    return __uint_as_float(u);
}

// ---------------- K0: reset scratch ----------------
__global__ void k0_init() {
    int i = blockIdx.x * 256 + threadIdx.x;
    if (i < BB * KK) g_cnt[i] = 0;
    if (i < BB * DD) g_maxu[i] = 0u;   // below all finite flipped floats
}

// ---------------- K1: argmax classify + compaction ----------------
__global__ void k1_classify(const float* __restrict__ lab) {
    __shared__ int scnt[KK];
    __shared__ int sbase[KK];
    int t   = threadIdx.x;
    int gid = blockIdx.x * 256 + t;
    int b   = gid / NN;
    int n   = gid % NN;

    if (t < KK) scnt[t] = 0;
    __syncthreads();

    const float* lb = lab + (size_t)b * KK * NN + n;
    float l0 = lb[0], l1 = lb[NN], l2 = lb[2 * NN], l3 = lb[3 * NN];
    int k = 0; float best = l0;
    if (l1 > best) { best = l1; k = 1; }
    if (l2 > best) { best = l2; k = 2; }
    if (l3 > best) { best = l3; k = 3; }

    int pos = atomicAdd(&scnt[k], 1);
    __syncthreads();
    if (t < KK) sbase[t] = atomicAdd(&g_cnt[b * KK + t], scnt[t]);
    __syncthreads();
    g_idx[(b * KK + k) * NN + sbase[k] + pos] = n;
}

// ---------------- K2: persistent, branch-pinned, W2 in SMEM ----------------
// 296 blocks (2 CTAs x 148 SMs), 256 threads. kb = blockIdx.x & 3 is FIXED per
// block; W2[kb] (64 KB) + W1/b1 are loaded into smem ONCE, then the block
// strides the 1024 (tile,b) slots of its branch. Hot loop has ZERO global
// loads: per kk = 1 LDS.128 (h) + 2 LDS.128 (W2s, broadcast conflict-free)
// + 4 dup movs + 16 FFMA2, software-pipelined 1 deep.
__global__ __launch_bounds__(256, 2)
void k2_main(const float* __restrict__ x,
             const float* __restrict__ W1, const float* __restrict__ b1,
             const float* __restrict__ W2, const float* __restrict__ b2) {
    extern __shared__ __align__(16) char smem[];
    float* W2s              = reinterpret_cast<float*>(smem + OFF_W2);
    float (*sh_ht)[TILE]    = reinterpret_cast<float(*)[TILE]>(smem + OFF_HT);
    float* sh_x0            = reinterpret_cast<float*>(smem + OFF_X0);
    float* sh_x1            = reinterpret_cast<float*>(smem + OFF_X1);
    float* sh_x2            = reinterpret_cast<float*>(smem + OFF_X2);
    int*   sh_idx           = reinterpret_cast<int*>  (smem + OFF_IDX);
    float* sh_w1            = reinterpret_cast<float*>(smem + OFF_W1);
    float* sh_b1            = reinterpret_cast<float*>(smem + OFF_B1);

    const int t     = threadIdx.x;
    const int kb    = blockIdx.x & 3;
    const int slot0 = blockIdx.x >> 2;       // 0..73
    const int dtile = t >> 3;                // 0..31
    const int prow  = t & 7;                 // 0..7
    const int d0    = dtile * 8;

    // one-time per-block loads: W2[kb] (coalesced 16B), W1[kb], b1[kb]
    {
        const float4* src = reinterpret_cast<const float4*>(W2 + (size_t)kb * HID * DD);
        float4* dst = reinterpret_cast<float4*>(W2s);
        #pragma unroll
        for (int i = 0; i < (HID * DD / 4) / 256; i++)
            dst[i * 256 + t] = src[i * 256 + t];
        if (t < CIN * HID) sh_w1[t] = W1[kb * CIN * HID + t];
        if (t < HID)       sh_b1[t] = b1[kb * HID + t];
    }
    __syncthreads();

    const float* wbase = W2s + d0;

    for (int it = slot0; it < SLOTS; it += BLKS_PER_KB) {
        const int tile = it >> 4;
        const int b    = it & 15;

        const int cnt   = g_cnt[b * KK + kb];
        const int start = tile * TILE;
        if (start >= cnt) continue;           // block-uniform branch
        const int npts = min(TILE, cnt - start);

        __syncthreads();   // previous item's phase-2 reads done before overwrite

        if (t < TILE && t < npts) sh_idx[t] = g_idx[(b * KK + kb) * NN + start + t];
        __syncthreads();

        if (t < npts) {
            int n = sh_idx[t];
            const float* xb = x + (size_t)b * CIN * NN;
            sh_x0[t] = xb[n];
            sh_x1[t] = xb[NN + n];
            sh_x2[t] = xb[2 * NN + n];
        }
        __syncthreads();

        // ---- phase 1: lane = point, jg = t>>5 covers 8 j's; zero-fill tail
        {
            const int lane = t & 31;
            const int jg   = t >> 5;            // 0..7
            #pragma unroll
            for (int pass = 0; pass < TILE / 32; pass++) {
                int pp = pass * 32 + lane;
                if (pp < npts) {
                    float x0 = sh_x0[pp], x1 = sh_x1[pp], x2 = sh_x2[pp];
                    #pragma unroll
                    for (int jj = 0; jj < 8; jj++) {
                        int j = jg * 8 + jj;
                        float v = fmaf(x0, sh_w1[j],
                                  fmaf(x1, sh_w1[HID + j],
                                  fmaf(x2, sh_w1[2 * HID + j], sh_b1[j])));
                        sh_ht[j][pp] = gelu_exact(v);
                    }
                } else {
                    #pragma unroll
                    for (int jj = 0; jj < 8; jj++)
                        sh_ht[jg * 8 + jj][pp] = 0.0f;
                }
            }
        }
        __syncthreads();

        // ---- phase 2: 8 dims x 4 points per thread, 4 passes, pipelined kk
        float mx[8];
        #pragma unroll
        for (int c = 0; c < 8; c++) mx[c] = -3.402823466e38f;

        #pragma unroll 1
        for (int pass = 0; pass < TILE / 32; pass++) {
            const int p0 = pass * 32 + prow * 4;
            const float* hcol = &sh_ht[0][p0];

            unsigned long long acc[4][4];   // [point][dim-pair]
            #pragma unroll
            for (int p = 0; p < 4; p++)
                #pragma unroll
                for (int c = 0; c < 4; c++) acc[p][c] = 0ull;

            // prologue: load kk = 0 (all smem)
            float4 ha      = *reinterpret_cast<const float4*>(hcol);
            ulonglong2 w03 = *reinterpret_cast<const ulonglong2*>(wbase);
            ulonglong2 w47 = *reinterpret_cast<const ulonglong2*>(wbase + 4);

            #pragma unroll 1
            for (int kk = 0; kk < HID - 1; kk++) {
                const float4 hc     = ha;
                const ulonglong2 wA = w03;
                const ulonglong2 wB = w47;
                // prefetch next iteration (overlaps with the FMAs below)
                ha  = *reinterpret_cast<const float4*>(hcol + (size_t)(kk + 1) * TILE);
                w03 = *reinterpret_cast<const ulonglong2*>(wbase + (size_t)(kk + 1) * DD);
                w47 = *reinterpret_cast<const ulonglong2*>(wbase + (size_t)(kk + 1) * DD + 4);

                const unsigned long long h0 = dup2(hc.x), h1 = dup2(hc.y),
                                         h2 = dup2(hc.z), h3 = dup2(hc.w);
                acc[0][0] = fma2(h0, wA.x, acc[0][0]);
                acc[0][1] = fma2(h0, wA.y, acc[0][1]);
                acc[0][2] = fma2(h0, wB.x, acc[0][2]);
                acc[0][3] = fma2(h0, wB.y, acc[0][3]);
                acc[1][0] = fma2(h1, wA.x, acc[1][0]);
                acc[1][1] = fma2(h1, wA.y, acc[1][1]);
                acc[1][2] = fma2(h1, wB.x, acc[1][2]);
                acc[1][3] = fma2(h1, wB.y, acc[1][3]);
                acc[2][0] = fma2(h2, wA.x, acc[2][0]);
                acc[2][1] = fma2(h2, wA.y, acc[2][1]);
                acc[2][2] = fma2(h2, wB.x, acc[2][2]);
                acc[2][3] = fma2(h2, wB.y, acc[2][3]);
                acc[3][0] = fma2(h3, wA.x, acc[3][0]);
                acc[3][1] = fma2(h3, wA.y, acc[3][1]);
                acc[3][2] = fma2(h3, wB.x, acc[3][2]);
                acc[3][3] = fma2(h3, wB.y, acc[3][3]);
            }
            // epilogue: kk = HID-1
            {
                const unsigned long long h0 = dup2(ha.x), h1 = dup2(ha.y),
                                         h2 = dup2(ha.z), h3 = dup2(ha.w);
                acc[0][0] = fma2(h0, w03.x, acc[0][0]);
                acc[0][1] = fma2(h0, w03.y, acc[0][1]);
                acc[0][2] = fma2(h0, w47.x, acc[0][2]);
                acc[0][3] = fma2(h0, w47.y, acc[0][3]);
                acc[1][0] = fma2(h1, w03.x, acc[1][0]);
                acc[1][1] = fma2(h1, w03.y, acc[1][1]);
                acc[1][2] = fma2(h1, w47.x, acc[1][2]);
                acc[1][3] = fma2(h1, w47.y, acc[1][3]);
                acc[2][0] = fma2(h2, w03.x, acc[2][0]);
                acc[2][1] = fma2(h2, w03.y, acc[2][1]);
                acc[2][2] = fma2(h2, w47.x, acc[2][2]);
                acc[2][3] = fma2(h2, w47.y, acc[2][3]);
                acc[3][0] = fma2(h3, w03.x, acc[3][0]);
                acc[3][1] = fma2(h3, w03.y, acc[3][1]);
                acc[3][2] = fma2(h3, w47.x, acc[3][2]);
                acc[3][3] = fma2(h3, w47.y, acc[3][3]);
            }

            // fold valid points of this pass into per-dim running max
            #pragma unroll
            for (int p = 0; p < 4; p++) {
                if (p0 + p < npts) {
                    #pragma unroll
                    for (int c = 0; c < 4; c++) {
                        float lo, hi; unpack2(acc[p][c], lo, hi);
                        mx[2 * c]     = fmaxf(mx[2 * c],     lo);
                        mx[2 * c + 1] = fmaxf(mx[2 * c + 1], hi);
                    }
                }
            }
        }

        // warp butterfly over prow bits (lanes sharing a dtile are adjacent)
        #pragma unroll
        for (int s = 1; s < 8; s <<= 1)
            #pragma unroll
            for (int c = 0; c < 8; c++)
                mx[c] = fmaxf(mx[c], __shfl_xor_sync(0xffffffffu, mx[c], s));

        if (prow == 0) {
            #pragma unroll
            for (int c = 0; c < 8; c++) {
                float v = mx[c] + b2[kb * DD + d0 + c];  // bias hoisted past max
                atomicMax(&g_maxu[b * DD + d0 + c], flip_f32(v));
            }
        }
    }
}

// ---------------- K3: global MLP on per-batch max ----------------
__global__ __launch_bounds__(1024, 1)
void k3_head(const float* __restrict__ Wg1, const float* __restrict__ bg1,
             const float* __restrict__ Wg2, const float* __restrict__ bg2,
             float* __restrict__ out) {
    __shared__ float sg[DD];
    __shared__ float part[1024];
    __shared__ float shg[GHID];
    const int b   = blockIdx.x;
    const int tid = threadIdx.x;
    const int t   = tid & 127;     // output unit
    const int g   = tid >> 7;      // j-split group 0..7

    if (tid < DD) sg[tid] = unflip_f32(g_maxu[b * DD + tid]);
    __syncthreads();

    // layer 1: 256 -> 128, each thread covers 32 j's
    {
        float acc = 0.0f;
        const int j0 = g * 32;
        #pragma unroll 16
        for (int j = 0; j < 32; j++)
            acc = fmaf(sg[j0 + j], Wg1[(j0 + j) * GHID + t], acc);
        part[tid] = acc;
    }
    __syncthreads();
    if (tid < GHID) {
        float v = bg1[tid];
        #pragma unroll
        for (int gg = 0; gg < 8; gg++) v += part[tid + 128 * gg];
        shg[tid] = gelu_exact(v);
    }
    __syncthreads();

    // layer 2: 128 -> 128, each thread covers 16 j's
    {
        float acc = 0.0f;
        const int j0 = g * 16;
        #pragma unroll 16
        for (int j = 0; j < 16; j++)
            acc = fmaf(shg[j0 + j], Wg2[(j0 + j) * DOUT + t], acc);
        part[tid] = acc;
    }
    __syncthreads();
    if (tid < DOUT) {
        float v = bg2[tid];
        #pragma unroll
        for (int gg = 0; gg < 8; gg++) v += part[tid + 128 * gg];
        out[b * DOUT + tid] = v;
    }
}

// ---------------- launch ----------------
extern "C" void kernel_launch(void* const* d_in, const int* in_sizes, int n_in,
                              void* d_out, int out_size) {
    const float* x     = (const float*)d_in[0];
    const float* xlab  = (const float*)d_in[1];
    const float* W1    = (const float*)d_in[2];
    const float* b1    = (const float*)d_in[3];
    const float* W2    = (const float*)d_in[4];
    const float* b2    = (const float*)d_in[5];
    const float* Wg1   = (const float*)d_in[6];
    const float* bg1   = (const float*)d_in[7];
    const float* Wg2   = (const float*)d_in[8];
    const float* bg2   = (const float*)d_in[9];
    float* out = (float*)d_out;

    // opt-in to 99 KB dynamic smem for k2 (idempotent; attribute set, not an
    // allocation — legal under the harness rules and during graph capture)
    cudaFuncSetAttribute(k2_main, cudaFuncAttributeMaxDynamicSharedMemorySize,
                         K2_SMEM);

    k0_init<<<(BB * DD + 255) / 256, 256>>>();
    k1_classify<<<(BB * NN) / 256, 256>>>(xlab);
    k2_main<<<PBLOCKS, 256, K2_SMEM>>>(x, W1, b1, W2, b2);
    k3_head<<<BB, 1024>>>(Wg1, bg1, Wg2, bg2, out);
}